// round 10
// baseline (speedup 1.0000x reference)
#include <cuda_runtime.h>
#include <cstdint>

#define N_ROWS      65536
#define DIM         256
#define NCODES      1024
#define BM          128
#define BK          64
#define HALF_CODES  512
#define XS_STR      132          // 128 + 4 pad (floats), 16B-aligned rows
#define DS_STR      68           // 64 + 4 pad
#define TPB         128          // 16 row-groups x 8 code-groups, 8x8 micro-tile
#define GTPB        256
#define NTILES      (N_ROWS / BM)        // 512 row tiles
#define NBLOCKS_MAIN (NTILES * 2)        // x2 code halves = 1024 blocks

// Scratch (no allocation allowed anywhere)
__device__ float g_dictT[NCODES * DIM];            // [k][d] for coalesced gather
__device__ float g_sume2[NCODES];                  // fl32 sequential sum e^2 per code
__device__ unsigned long long g_best[N_ROWS];      // global argmin keys
__device__ float g_partial[NTILES];                // per-tile loss partials

// ---------------------------------------------------------------------------
// Init A: transpose dictionary
// ---------------------------------------------------------------------------
__global__ void vq_transpose(const float* __restrict__ dict) {
    int k = blockIdx.x;
    int d = threadIdx.x;
    g_dictT[k * DIM + d] = dict[d * NCODES + k];
}

// ---------------------------------------------------------------------------
// Init B: sum(e^2) axis 0 — sequential, separate mul/add roundings (no fma)
// ---------------------------------------------------------------------------
__global__ void vq_sume2(const float* __restrict__ dict) {
    int k = blockIdx.x * blockDim.x + threadIdx.x;
    if (k >= NCODES) return;
    float s = 0.0f;
    for (int d = 0; d < DIM; d++) {
        float e = dict[d * NCODES + k];
        s = __fadd_rn(s, __fmul_rn(e, e));
    }
    g_sume2[k] = s;
}

// ---------------------------------------------------------------------------
// Init C: reset global argmin keys (graph replays -> must reset every launch)
// ---------------------------------------------------------------------------
__global__ void vq_reset() {
    int i = blockIdx.x * blockDim.x + threadIdx.x;
    g_best[i] = 0xFFFFFFFFFFFFFFFFull;
}

// monotone-increasing map f32 -> u32 (argmin via unsigned min)
__device__ __forceinline__ unsigned enc_f(float s) {
    unsigned u = __float_as_uint(s);
    return (u & 0x80000000u) ? ~u : (u | 0x80000000u);
}

// packed helpers
__device__ __forceinline__ unsigned long long bcast2(float v) {
    unsigned long long r;
    asm("mov.b64 %0, {%1, %1};" : "=l"(r) : "f"(v));
    return r;
}
__device__ __forceinline__ void ffma2(unsigned long long& acc,
                                      unsigned long long a, unsigned long long b) {
    // packed f32x2 FMA: each lane IEEE rn — bitwise identical to two FFMAs
    asm("fma.rn.f32x2 %0, %1, %2, %0;" : "+l"(acc) : "l"(a), "l"(b));
}
__device__ __forceinline__ void unpack2(unsigned long long p, float& lo, float& hi) {
    asm("mov.b64 {%0, %1}, %2;" : "=f"(lo), "=f"(hi) : "l"(p));
}

// ---------------------------------------------------------------------------
// Main: 128-row x 512-code tile per block, 128 threads (4 warps, 1/SMSP).
// Per thread: 8 rows (4 packed row-pairs) x 8 codes -> 32 FFMA2 per d from
// only 4 LDS.128 -> FFMA2:LDS.128 = 8:1 = SM pipe balance point.
// Each packed lane is one output's sequential FFMA chain over d=0..255
// (bit-identical to reference); reference-exact distance rounding; argmin.
// ---------------------------------------------------------------------------
// smem floats: Xs(DIM*XS_STR) Ds(DIM*DS_STR) se(NCODES) Ss(BM) bestsh(BM ull)
#define SMEM_FLOATS (DIM * XS_STR + DIM * DS_STR + NCODES + BM + 2 * BM)
#define SMEM_BYTES  (SMEM_FLOATS * 4)

extern __shared__ float smem_f[];

__global__ void __launch_bounds__(TPB, 1) vq_main(const float* __restrict__ x,
                                                  const float* __restrict__ dict) {
    float* Xs = smem_f;
    float* Ds = Xs + DIM * XS_STR;
    float* se = Ds + DIM * DS_STR;
    float* Ss = se + NCODES;
    unsigned long long* bestsh = (unsigned long long*)(Ss + BM);

    const int tid  = threadIdx.x;
    const int rt   = blockIdx.x >> 1;        // row tile
    const int half = blockIdx.x & 1;         // code half
    const int m0   = rt * BM;
    const int k0   = half * HALF_CODES;

    // --- load x tile [BM][DIM], store transposed [d][m] ---
    const float4* x4 = (const float4*)(x + (size_t)m0 * DIM);
    #pragma unroll 4
    for (int t = tid; t < BM * DIM / 4; t += TPB) {
        int m  = t >> 6;          // 64 float4 per row
        int c4 = t & 63;
        float4 v = x4[t];
        int d = c4 * 4;
        Xs[(d + 0) * XS_STR + m] = v.x;
        Xs[(d + 1) * XS_STR + m] = v.y;
        Xs[(d + 2) * XS_STR + m] = v.z;
        Xs[(d + 3) * XS_STR + m] = v.w;
    }
    for (int i = tid; i < NCODES; i += TPB) se[i] = g_sume2[i];
    if (tid < BM) bestsh[tid] = 0xFFFFFFFFFFFFFFFFull;
    __syncthreads();

    // --- S = sum(x_row^2): same bit-exact emulation (XLA warp row-reduce):
    //     lane t sums d = t, t+32, ..., t+224 (mul+add, no fma), shfl tree.
    {
        int warp = tid >> 5, lane = tid & 31;      // 4 warps x 32 rows
        #pragma unroll
        for (int r = 0; r < BM / 4; r++) {
            int row = warp * (BM / 4) + r;
            float p = 0.0f;
            #pragma unroll
            for (int i = 0; i < 8; i++) {
                float v = Xs[(lane + 32 * i) * XS_STR + row];
                p = __fadd_rn(p, __fmul_rn(v, v));
            }
            #pragma unroll
            for (int o = 16; o > 0; o >>= 1)
                p = __fadd_rn(p, __shfl_xor_sync(0xFFFFFFFFu, p, o));
            if (lane == 0) Ss[row] = p;
        }
    }
    __syncthreads();

    const int tx = tid & 7;     // 8 code groups x 8 codes = 64 (BK)
    const int ty = tid >> 3;    // 16 row groups x 8 rows  = 128 (BM)

    float Srow[8];
    #pragma unroll
    for (int i = 0; i < 8; i++) Srow[i] = Ss[ty * 8 + i];

    unsigned long long kmin[8];
    #pragma unroll
    for (int i = 0; i < 8; i++) kmin[i] = 0xFFFFFFFFFFFFFFFFull;

    for (int kc = 0; kc < HALF_CODES / BK; kc++) {
        // load dict chunk [DIM][BK] via float4, coalesced
        #pragma unroll 4
        for (int t = tid; t < DIM * BK / 4; t += TPB) {
            int d  = t >> 4;          // 16 float4 per d-row
            int k4 = t & 15;
            float4 v = *(const float4*)&dict[d * NCODES + k0 + kc * BK + k4 * 4];
            *(float4*)&Ds[d * DS_STR + k4 * 4] = v;
        }
        __syncthreads();

        // acc2[rowpair][code]: packed lanes = (row 2rp, row 2rp+1)
        unsigned long long acc2[4][8];
        #pragma unroll
        for (int i = 0; i < 4; i++)
            #pragma unroll
            for (int j = 0; j < 8; j++) acc2[i][j] = 0ULL;

        #pragma unroll 2
        for (int d = 0; d < DIM; d++) {
            ulonglong2 a01 = *(const ulonglong2*)&Xs[d * XS_STR + ty * 8];
            ulonglong2 a23 = *(const ulonglong2*)&Xs[d * XS_STR + ty * 8 + 4];
            float4 bA = *(const float4*)&Ds[d * DS_STR + tx * 8];
            float4 bB = *(const float4*)&Ds[d * DS_STR + tx * 8 + 4];
            unsigned long long b0 = bcast2(bA.x);
            unsigned long long b1 = bcast2(bA.y);
            unsigned long long b2 = bcast2(bA.z);
            unsigned long long b3 = bcast2(bA.w);
            unsigned long long b4 = bcast2(bB.x);
            unsigned long long b5 = bcast2(bB.y);
            unsigned long long b6 = bcast2(bB.z);
            unsigned long long b7 = bcast2(bB.w);
            ffma2(acc2[0][0], a01.x, b0); ffma2(acc2[0][1], a01.x, b1);
            ffma2(acc2[0][2], a01.x, b2); ffma2(acc2[0][3], a01.x, b3);
            ffma2(acc2[0][4], a01.x, b4); ffma2(acc2[0][5], a01.x, b5);
            ffma2(acc2[0][6], a01.x, b6); ffma2(acc2[0][7], a01.x, b7);
            ffma2(acc2[1][0], a01.y, b0); ffma2(acc2[1][1], a01.y, b1);
            ffma2(acc2[1][2], a01.y, b2); ffma2(acc2[1][3], a01.y, b3);
            ffma2(acc2[1][4], a01.y, b4); ffma2(acc2[1][5], a01.y, b5);
            ffma2(acc2[1][6], a01.y, b6); ffma2(acc2[1][7], a01.y, b7);
            ffma2(acc2[2][0], a23.x, b0); ffma2(acc2[2][1], a23.x, b1);
            ffma2(acc2[2][2], a23.x, b2); ffma2(acc2[2][3], a23.x, b3);
            ffma2(acc2[2][4], a23.x, b4); ffma2(acc2[2][5], a23.x, b5);
            ffma2(acc2[2][6], a23.x, b6); ffma2(acc2[2][7], a23.x, b7);
            ffma2(acc2[3][0], a23.y, b0); ffma2(acc2[3][1], a23.y, b1);
            ffma2(acc2[3][2], a23.y, b2); ffma2(acc2[3][3], a23.y, b3);
            ffma2(acc2[3][4], a23.y, b4); ffma2(acc2[3][5], a23.y, b5);
            ffma2(acc2[3][6], a23.y, b6); ffma2(acc2[3][7], a23.y, b7);
        }

        // reference-exact distance: D = fl( fl(S + se_k) - 2*sim )
        #pragma unroll
        for (int rp = 0; rp < 4; rp++) {
            #pragma unroll
            for (int j = 0; j < 8; j++) {
                int k = k0 + kc * BK + tx * 8 + j;
                float slo, shi;
                unpack2(acc2[rp][j], slo, shi);
                float T0 = __fadd_rn(Srow[rp * 2 + 0], se[k]);
                float D0 = __fadd_rn(T0, -2.0f * slo);
                unsigned long long key0 =
                    ((unsigned long long)enc_f(D0) << 32) | (unsigned long long)(unsigned)k;
                if (key0 < kmin[rp * 2 + 0]) kmin[rp * 2 + 0] = key0;
                float T1 = __fadd_rn(Srow[rp * 2 + 1], se[k]);
                float D1 = __fadd_rn(T1, -2.0f * shi);
                unsigned long long key1 =
                    ((unsigned long long)enc_f(D1) << 32) | (unsigned long long)(unsigned)k;
                if (key1 < kmin[rp * 2 + 1]) kmin[rp * 2 + 1] = key1;
            }
        }
        __syncthreads();   // protects Ds reuse
    }

    // block-local merge (order-independent min), then one global atomic per row
    #pragma unroll
    for (int i = 0; i < 8; i++) atomicMin(&bestsh[ty * 8 + i], kmin[i]);
    __syncthreads();
    if (tid < BM) atomicMin(&g_best[m0 + tid], bestsh[tid]);
}

// ---------------------------------------------------------------------------
// Gather: codes -> quantized output + per-tile loss partial (deterministic)
// ---------------------------------------------------------------------------
__global__ void __launch_bounds__(GTPB) vq_gather(const float* __restrict__ x,
                                                  float* __restrict__ out) {
    __shared__ int codes[BM];
    __shared__ float redf[GTPB];
    const int tid = threadIdx.x;
    const int m0  = blockIdx.x * BM;

    if (tid < BM)
        codes[tid] = (int)(unsigned)(g_best[m0 + tid] & 0xFFFFFFFFull);
    __syncthreads();

    const float4* x4 = (const float4*)x;
    float4* out4 = (float4*)out;
    float lsum = 0.0f;
    #pragma unroll 4
    for (int t = tid; t < BM * DIM / 4; t += GTPB) {
        int m  = t >> 6;
        int d4 = t & 63;
        float4 v  = *(const float4*)&g_dictT[codes[m] * DIM + d4 * 4];
        size_t gi = (size_t)(m0 + m) * (DIM / 4) + d4;
        float4 xv = x4[gi];
        float dx = xv.x - v.x, dy = xv.y - v.y, dz = xv.z - v.z, dw = xv.w - v.w;
        lsum += dx * dx + dy * dy + dz * dz + dw * dw;
        out4[gi] = v;
    }
    redf[tid] = lsum;
    __syncthreads();
    #pragma unroll
    for (int s = GTPB / 2; s > 0; s >>= 1) {
        if (tid < s) redf[tid] += redf[tid + s];
        __syncthreads();
    }
    if (tid == 0) g_partial[blockIdx.x] = redf[0];
}

// ---------------------------------------------------------------------------
// Final loss: loss = fl( m + fl(0.25*m) ), m = mean((x-q)^2) (f64 reduce)
// ---------------------------------------------------------------------------
__global__ void vq_finish(float* __restrict__ out, int out_size) {
    __shared__ double rd[GTPB];
    int tid = threadIdx.x;
    double s = 0.0;
    for (int i = tid; i < NTILES; i += GTPB) s += (double)g_partial[i];
    rd[tid] = s;
    __syncthreads();
    #pragma unroll
    for (int st = GTPB / 2; st > 0; st >>= 1) {
        if (tid < st) rd[tid] += rd[tid + st];
        __syncthreads();
    }
    if (tid == 0 && out_size > N_ROWS * DIM) {
        double mse = rd[0] / (double)((size_t)N_ROWS * DIM);
        float m = (float)mse;
        out[N_ROWS * DIM] = __fadd_rn(m, __fmul_rn(0.25f, m));
    }
}

// ---------------------------------------------------------------------------
extern "C" void kernel_launch(void* const* d_in, const int* in_sizes, int n_in,
                              void* d_out, int out_size) {
    const float* x    = (const float*)d_in[0];   // [16,64,64,256] f32
    const float* dict = (const float*)d_in[1];   // [256,1024]     f32
    float* out = (float*)d_out;

    cudaFuncSetAttribute(vq_main, cudaFuncAttributeMaxDynamicSharedMemorySize, SMEM_BYTES);

    vq_transpose<<<NCODES, DIM>>>(dict);
    vq_sume2<<<NCODES / GTPB, GTPB>>>(dict);
    vq_reset<<<N_ROWS / GTPB, GTPB>>>();
    vq_main<<<NBLOCKS_MAIN, TPB, SMEM_BYTES>>>(x, dict);
    vq_gather<<<NTILES, GTPB>>>(x, out);
    vq_finish<<<1, GTPB>>>(out, out_size);
}

// round 12
// speedup vs baseline: 1.0072x; 1.0072x over previous
#include <cuda_runtime.h>
#include <cstdint>

#define N_ROWS      65536
#define DIM         256
#define NCODES      1024
#define BM          128
#define BK          128
#define DCH         128          // d-chunk
#define XS_STR      132
#define DS_STR      132
#define TPB         256
#define GTPB        256
#define NTILES      (N_ROWS / BM)            // 512 row tiles
#define NBLOCKS_MAIN (NTILES * (NCODES / BK))  // 512 x 8 = 4096

// Scratch (static device globals only — no allocation)
__device__ float g_xT[(size_t)DIM * N_ROWS];       // x transposed [d][m] (64MB)
__device__ float g_dictT[NCODES * DIM];            // [k][d] for coalesced gather
__device__ float g_sume2[NCODES];                  // fl32 sequential sum e^2
__device__ float g_S[N_ROWS];                      // reference-emulated row norms
__device__ unsigned long long g_best[N_ROWS];      // global argmin keys
__device__ float g_partial[NTILES];                // per-tile loss partials

// ---------------------------------------------------------------------------
// Init A: transpose dictionary (for gather)
// ---------------------------------------------------------------------------
__global__ void vq_transpose(const float* __restrict__ dict) {
    int k = blockIdx.x;
    int d = threadIdx.x;
    g_dictT[k * DIM + d] = dict[d * NCODES + k];
}

// ---------------------------------------------------------------------------
// Init B: sum(e^2) axis 0 — sequential, separate mul/add roundings (no fma)
// ---------------------------------------------------------------------------
__global__ void vq_sume2(const float* __restrict__ dict) {
    int k = blockIdx.x * blockDim.x + threadIdx.x;
    if (k >= NCODES) return;
    float s = 0.0f;
    for (int d = 0; d < DIM; d++) {
        float e = dict[d * NCODES + k];
        s = __fadd_rn(s, __fmul_rn(e, e));
    }
    g_sume2[k] = s;
}

// ---------------------------------------------------------------------------
// Init C: full x transpose -> g_xT[d][m]  (classic 32x32 smem transpose)
// ---------------------------------------------------------------------------
__global__ void vq_xT(const float* __restrict__ x) {
    __shared__ float ts[32][33];
    int mb = blockIdx.x * 32, db = blockIdx.y * 32;
    #pragma unroll
    for (int r = threadIdx.y; r < 32; r += 8)
        ts[r][threadIdx.x] = x[(size_t)(mb + r) * DIM + db + threadIdx.x];
    __syncthreads();
    #pragma unroll
    for (int r = threadIdx.y; r < 32; r += 8)
        g_xT[(size_t)(db + r) * N_ROWS + mb + threadIdx.x] = ts[threadIdx.x][r];
}

// ---------------------------------------------------------------------------
// Init D: S = sum(x_row^2), bit-exact XLA warp row-reduce emulation:
//         lane t sums d = t, t+32, ..., t+224 (mul+add, no fma), shfl tree.
// ---------------------------------------------------------------------------
__global__ void vq_rownorm(const float* __restrict__ x) {
    int warp = threadIdx.x >> 5, lane = threadIdx.x & 31;
    int row0 = blockIdx.x * 32 + warp * 4;      // 8 warps x 4 rows
    #pragma unroll
    for (int r = 0; r < 4; r++) {
        int row = row0 + r;
        float p = 0.0f;
        #pragma unroll
        for (int i = 0; i < 8; i++) {
            float v = x[(size_t)row * DIM + lane + 32 * i];
            p = __fadd_rn(p, __fmul_rn(v, v));
        }
        #pragma unroll
        for (int o = 16; o > 0; o >>= 1)
            p = __fadd_rn(p, __shfl_xor_sync(0xFFFFFFFFu, p, o));
        if (lane == 0) g_S[row] = p;
    }
}

// ---------------------------------------------------------------------------
// Init E: reset global argmin keys (graph replays -> reset every launch)
// ---------------------------------------------------------------------------
__global__ void vq_reset() {
    int i = blockIdx.x * blockDim.x + threadIdx.x;
    g_best[i] = 0xFFFFFFFFFFFFFFFFull;
}

// monotone-increasing map f32 -> u32 (argmin via unsigned min)
__device__ __forceinline__ unsigned enc_f(float s) {
    unsigned u = __float_as_uint(s);
    return (u & 0x80000000u) ? ~u : (u | 0x80000000u);
}

// packed helpers
__device__ __forceinline__ unsigned long long bcast2(float v) {
    unsigned long long r;
    asm("mov.b64 %0, {%1, %1};" : "=l"(r) : "f"(v));
    return r;
}
__device__ __forceinline__ void ffma2(unsigned long long& acc,
                                      unsigned long long a, unsigned long long b) {
    // packed f32x2 FMA: each lane IEEE rn — bitwise identical to two FFMAs
    asm("fma.rn.f32x2 %0, %1, %2, %0;" : "+l"(acc) : "l"(a), "l"(b));
}
__device__ __forceinline__ void unpack2(unsigned long long p, float& lo, float& hi) {
    asm("mov.b64 {%0, %1}, %2;" : "=f"(lo), "=f"(hi) : "l"(p));
}

// ---------------------------------------------------------------------------
// Main: 128-row x 128-code block, 256 threads (8 warps, 2/SMSP).
// d processed in two 128-chunks; accumulators persist in registers so each
// packed lane remains ONE sequential FFMA chain over d=0..255 (bit-identical
// to reference). Per thread 8x8 micro-tile: 32 FFMA2 from 4 LDS.128 per d.
// ---------------------------------------------------------------------------
// smem floats: Xs(DCH*XS_STR) Ds(DCH*DS_STR) se(BK) bestsh(BM ull)
#define SMEM_FLOATS (DCH * XS_STR + DCH * DS_STR + BK + 2 * BM)
#define SMEM_BYTES  (SMEM_FLOATS * 4)

extern __shared__ float smem_f[];

__global__ void __launch_bounds__(TPB, 1) vq_main(const float* __restrict__ dict) {
    float* Xs = smem_f;
    float* Ds = Xs + DCH * XS_STR;
    float* se = Ds + DCH * DS_STR;
    unsigned long long* bestsh = (unsigned long long*)(se + BK);

    const int tid = threadIdx.x;
    const int rt  = blockIdx.x >> 3;         // row tile   (adjacent bids share rt -> L2 reuse)
    const int cc  = blockIdx.x & 7;          // code chunk
    const int m0  = rt * BM;
    const int k0  = cc * BK;

    if (tid < BK) se[tid] = g_sume2[k0 + tid];
    if (tid < BM) bestsh[tid] = 0xFFFFFFFFFFFFFFFFull;

    const int tx = tid & 15;    // 16 code groups x 8 codes = 128 (BK)
    const int ty = tid >> 4;    // 16 row groups  x 8 rows  = 128 (BM)

    // acc2[rowpair][code]: packed lanes = (row ty*8+2rp, +2rp+1)
    unsigned long long acc2[4][8];
    #pragma unroll
    for (int i = 0; i < 4; i++)
        #pragma unroll
        for (int j = 0; j < 8; j++) acc2[i][j] = 0ULL;

    for (int ch = 0; ch < DIM / DCH; ch++) {
        __syncthreads();    // protect smem reuse from previous chunk

        // Xs chunk: straight copy from g_xT (conflict-free both sides)
        #pragma unroll 4
        for (int t = tid; t < DCH * (BM / 4); t += TPB) {
            int d  = t >> 5;            // 32 float4 per d-row
            int m4 = t & 31;
            *(float4*)&Xs[d * XS_STR + m4 * 4] =
                *(const float4*)&g_xT[(size_t)(ch * DCH + d) * N_ROWS + m0 + m4 * 4];
        }
        // Ds chunk, split-half layout: codes j<4 of group g at col g*4,
        // j>=4 at 64 + g*4  -> both b-loads are 16B-stride, conflict-free
        #pragma unroll 4
        for (int t = tid; t < DCH * (BK / 4); t += TPB) {
            int d  = t >> 5;
            int k4 = t & 31;
            int col = ((k4 & 1) << 6) + ((k4 >> 1) << 2);
            *(float4*)&Ds[d * DS_STR + col] =
                *(const float4*)&dict[(size_t)(ch * DCH + d) * NCODES + k0 + k4 * 4];
        }
        __syncthreads();

        #pragma unroll 2
        for (int d = 0; d < DCH; d++) {
            ulonglong2 a01 = *(const ulonglong2*)&Xs[d * XS_STR + ty * 8];
            ulonglong2 a23 = *(const ulonglong2*)&Xs[d * XS_STR + ty * 8 + 4];
            float4 bA = *(const float4*)&Ds[d * DS_STR + tx * 4];
            float4 bB = *(const float4*)&Ds[d * DS_STR + 64 + tx * 4];
            unsigned long long b0 = bcast2(bA.x);
            unsigned long long b1 = bcast2(bA.y);
            unsigned long long b2 = bcast2(bA.z);
            unsigned long long b3 = bcast2(bA.w);
            unsigned long long b4 = bcast2(bB.x);
            unsigned long long b5 = bcast2(bB.y);
            unsigned long long b6 = bcast2(bB.z);
            unsigned long long b7 = bcast2(bB.w);
            ffma2(acc2[0][0], a01.x, b0); ffma2(acc2[0][1], a01.x, b1);
            ffma2(acc2[0][2], a01.x, b2); ffma2(acc2[0][3], a01.x, b3);
            ffma2(acc2[0][4], a01.x, b4); ffma2(acc2[0][5], a01.x, b5);
            ffma2(acc2[0][6], a01.x, b6); ffma2(acc2[0][7], a01.x, b7);
            ffma2(acc2[1][0], a01.y, b0); ffma2(acc2[1][1], a01.y, b1);
            ffma2(acc2[1][2], a01.y, b2); ffma2(acc2[1][3], a01.y, b3);
            ffma2(acc2[1][4], a01.y, b4); ffma2(acc2[1][5], a01.y, b5);
            ffma2(acc2[1][6], a01.y, b6); ffma2(acc2[1][7], a01.y, b7);
            ffma2(acc2[2][0], a23.x, b0); ffma2(acc2[2][1], a23.x, b1);
            ffma2(acc2[2][2], a23.x, b2); ffma2(acc2[2][3], a23.x, b3);
            ffma2(acc2[2][4], a23.x, b4); ffma2(acc2[2][5], a23.x, b5);
            ffma2(acc2[2][6], a23.x, b6); ffma2(acc2[2][7], a23.x, b7);
            ffma2(acc2[3][0], a23.y, b0); ffma2(acc2[3][1], a23.y, b1);
            ffma2(acc2[3][2], a23.y, b2); ffma2(acc2[3][3], a23.y, b3);
            ffma2(acc2[3][4], a23.y, b4); ffma2(acc2[3][5], a23.y, b5);
            ffma2(acc2[3][6], a23.y, b6); ffma2(acc2[3][7], a23.y, b7);
        }
    }

    // reference-exact distance: D = fl( fl(S + se_k) - 2*sim ), argmin w/ index
    float Srow[8];
    #pragma unroll
    for (int i = 0; i < 8; i++) Srow[i] = g_S[m0 + ty * 8 + i];

    unsigned long long kmin[8];
    #pragma unroll
    for (int i = 0; i < 8; i++) kmin[i] = 0xFFFFFFFFFFFFFFFFull;

    #pragma unroll
    for (int rp = 0; rp < 4; rp++) {
        #pragma unroll
        for (int j = 0; j < 8; j++) {
            int k = k0 + tx * 8 + j;
            float slo, shi;
            unpack2(acc2[rp][j], slo, shi);
            float T0 = __fadd_rn(Srow[rp * 2 + 0], se[tx * 8 + j]);
            float D0 = __fadd_rn(T0, -2.0f * slo);
            unsigned long long key0 =
                ((unsigned long long)enc_f(D0) << 32) | (unsigned long long)(unsigned)k;
            if (key0 < kmin[rp * 2 + 0]) kmin[rp * 2 + 0] = key0;
            float T1 = __fadd_rn(Srow[rp * 2 + 1], se[tx * 8 + j]);
            float D1 = __fadd_rn(T1, -2.0f * shi);
            unsigned long long key1 =
                ((unsigned long long)enc_f(D1) << 32) | (unsigned long long)(unsigned)k;
            if (key1 < kmin[rp * 2 + 1]) kmin[rp * 2 + 1] = key1;
        }
    }

    // block-local merge (order-independent min), then one global atomic per row
    #pragma unroll
    for (int i = 0; i < 8; i++) atomicMin(&bestsh[ty * 8 + i], kmin[i]);
    __syncthreads();
    if (tid < BM) atomicMin(&g_best[m0 + tid], bestsh[tid]);
}

// ---------------------------------------------------------------------------
// Gather: codes -> quantized output + per-tile loss partial (deterministic)
// ---------------------------------------------------------------------------
__global__ void __launch_bounds__(GTPB) vq_gather(const float* __restrict__ x,
                                                  float* __restrict__ out) {
    __shared__ int codes[BM];
    __shared__ float redf[GTPB];
    const int tid = threadIdx.x;
    const int m0  = blockIdx.x * BM;

    if (tid < BM)
        codes[tid] = (int)(unsigned)(g_best[m0 + tid] & 0xFFFFFFFFull);
    __syncthreads();

    const float4* x4 = (const float4*)x;
    float4* out4 = (float4*)out;
    float lsum = 0.0f;
    #pragma unroll 4
    for (int t = tid; t < BM * DIM / 4; t += GTPB) {
        int m  = t >> 6;
        int d4 = t & 63;
        float4 v  = *(const float4*)&g_dictT[codes[m] * DIM + d4 * 4];
        size_t gi = (size_t)(m0 + m) * (DIM / 4) + d4;
        float4 xv = x4[gi];
        float dx = xv.x - v.x, dy = xv.y - v.y, dz = xv.z - v.z, dw = xv.w - v.w;
        lsum += dx * dx + dy * dy + dz * dz + dw * dw;
        out4[gi] = v;
    }
    redf[tid] = lsum;
    __syncthreads();
    #pragma unroll
    for (int s = GTPB / 2; s > 0; s >>= 1) {
        if (tid < s) redf[tid] += redf[tid + s];
        __syncthreads();
    }
    if (tid == 0) g_partial[blockIdx.x] = redf[0];
}

// ---------------------------------------------------------------------------
// Final loss: loss = fl( m + fl(0.25*m) ), m = mean((x-q)^2) (f64 reduce)
// ---------------------------------------------------------------------------
__global__ void vq_finish(float* __restrict__ out, int out_size) {
    __shared__ double rd[GTPB];
    int tid = threadIdx.x;
    double s = 0.0;
    for (int i = tid; i < NTILES; i += GTPB) s += (double)g_partial[i];
    rd[tid] = s;
    __syncthreads();
    #pragma unroll
    for (int st = GTPB / 2; st > 0; st >>= 1) {
        if (tid < st) rd[tid] += rd[tid + st];
        __syncthreads();
    }
    if (tid == 0 && out_size > N_ROWS * DIM) {
        double mse = rd[0] / (double)((size_t)N_ROWS * DIM);
        float m = (float)mse;
        out[N_ROWS * DIM] = __fadd_rn(m, __fmul_rn(0.25f, m));
    }
}

// ---------------------------------------------------------------------------
extern "C" void kernel_launch(void* const* d_in, const int* in_sizes, int n_in,
                              void* d_out, int out_size) {
    const float* x    = (const float*)d_in[0];   // [16,64,64,256] f32
    const float* dict = (const float*)d_in[1];   // [256,1024]     f32
    float* out = (float*)d_out;

    cudaFuncSetAttribute(vq_main, cudaFuncAttributeMaxDynamicSharedMemorySize, SMEM_BYTES);

    vq_transpose<<<NCODES, DIM>>>(dict);
    vq_sume2<<<NCODES / GTPB, GTPB>>>(dict);
    {
        dim3 tb(32, 8);
        dim3 tg(N_ROWS / 32, DIM / 32);
        vq_xT<<<tg, tb>>>(x);
    }
    vq_rownorm<<<N_ROWS / 32, 256>>>(x);
    vq_reset<<<N_ROWS / GTPB, GTPB>>>();
    vq_main<<<NBLOCKS_MAIN, TPB, SMEM_BYTES>>>(dict);
    vq_gather<<<NTILES, GTPB>>>(x, out);
    vq_finish<<<1, GTPB>>>(out, out_size);
}

// round 13
// speedup vs baseline: 1.0840x; 1.0763x over previous
#include <cuda_runtime.h>
#include <cstdint>

#define N_ROWS      65536
#define DIM         256
#define NCODES      1024
#define BM          128
#define BK          128
#define DCH         64           // d-chunk (4 chunks) -> smem fits 2 CTAs/SM
#define XS_STR      132
#define DS_STR      132
#define TPB         256
#define GTPB        256
#define NTILES      (N_ROWS / BM)              // 512 row tiles
#define NBLOCKS_MAIN (NTILES * (NCODES / BK))  // 512 x 8 = 4096

// Scratch (static device globals only — no allocation)
__device__ float g_xT[(size_t)DIM * N_ROWS];       // x transposed [d][m] (64MB)
__device__ float g_dictT[NCODES * DIM];            // [k][d] for coalesced gather
__device__ float g_sume2[NCODES];                  // fl32 sequential sum e^2
__device__ float g_S[N_ROWS];                      // reference-emulated row norms
__device__ unsigned long long g_best[N_ROWS];      // global argmin keys
__device__ float g_partial[NTILES];                // per-tile loss partials

// ---------------------------------------------------------------------------
// Init A: transpose dictionary (for gather)
// ---------------------------------------------------------------------------
__global__ void vq_transpose(const float* __restrict__ dict) {
    int k = blockIdx.x;
    int d = threadIdx.x;
    g_dictT[k * DIM + d] = dict[d * NCODES + k];
}

// ---------------------------------------------------------------------------
// Init B: sum(e^2) axis 0 — sequential, separate mul/add roundings (no fma)
// ---------------------------------------------------------------------------
__global__ void vq_sume2(const float* __restrict__ dict) {
    int k = blockIdx.x * blockDim.x + threadIdx.x;
    if (k >= NCODES) return;
    float s = 0.0f;
    for (int d = 0; d < DIM; d++) {
        float e = dict[d * NCODES + k];
        s = __fadd_rn(s, __fmul_rn(e, e));
    }
    g_sume2[k] = s;
}

// ---------------------------------------------------------------------------
// Init C: full x transpose -> g_xT[d][m]  (classic 32x32 smem transpose)
// ---------------------------------------------------------------------------
__global__ void vq_xT(const float* __restrict__ x) {
    __shared__ float ts[32][33];
    int mb = blockIdx.x * 32, db = blockIdx.y * 32;
    #pragma unroll
    for (int r = threadIdx.y; r < 32; r += 8)
        ts[r][threadIdx.x] = x[(size_t)(mb + r) * DIM + db + threadIdx.x];
    __syncthreads();
    #pragma unroll
    for (int r = threadIdx.y; r < 32; r += 8)
        g_xT[(size_t)(db + r) * N_ROWS + mb + threadIdx.x] = ts[threadIdx.x][r];
}

// ---------------------------------------------------------------------------
// Init D: S = sum(x_row^2), bit-exact XLA warp row-reduce emulation:
//         lane t sums d = t, t+32, ..., t+224 (mul+add, no fma), shfl tree.
// ---------------------------------------------------------------------------
__global__ void vq_rownorm(const float* __restrict__ x) {
    int warp = threadIdx.x >> 5, lane = threadIdx.x & 31;
    int row0 = blockIdx.x * 32 + warp * 4;      // 8 warps x 4 rows
    #pragma unroll
    for (int r = 0; r < 4; r++) {
        int row = row0 + r;
        float p = 0.0f;
        #pragma unroll
        for (int i = 0; i < 8; i++) {
            float v = x[(size_t)row * DIM + lane + 32 * i];
            p = __fadd_rn(p, __fmul_rn(v, v));
        }
        #pragma unroll
        for (int o = 16; o > 0; o >>= 1)
            p = __fadd_rn(p, __shfl_xor_sync(0xFFFFFFFFu, p, o));
        if (lane == 0) g_S[row] = p;
    }
}

// ---------------------------------------------------------------------------
// Init E: reset global argmin keys (graph replays -> reset every launch)
// ---------------------------------------------------------------------------
__global__ void vq_reset() {
    int i = blockIdx.x * blockDim.x + threadIdx.x;
    g_best[i] = 0xFFFFFFFFFFFFFFFFull;
}

// monotone-increasing map f32 -> u32 (argmin via unsigned min)
__device__ __forceinline__ unsigned enc_f(float s) {
    unsigned u = __float_as_uint(s);
    return (u & 0x80000000u) ? ~u : (u | 0x80000000u);
}

// packed helpers
__device__ __forceinline__ unsigned long long bcast2(float v) {
    unsigned long long r;
    asm("mov.b64 %0, {%1, %1};" : "=l"(r) : "f"(v));
    return r;
}
__device__ __forceinline__ void ffma2(unsigned long long& acc,
                                      unsigned long long a, unsigned long long b) {
    // packed f32x2 FMA: each lane IEEE rn — bitwise identical to two FFMAs
    asm("fma.rn.f32x2 %0, %1, %2, %0;" : "+l"(acc) : "l"(a), "l"(b));
}
__device__ __forceinline__ void unpack2(unsigned long long p, float& lo, float& hi) {
    asm("mov.b64 {%0, %1}, %2;" : "=f"(lo), "=f"(hi) : "l"(p));
}

// ---------------------------------------------------------------------------
// Main: 128-row x 128-code block, 256 threads, 2 CTAs/SM (4 warps/SMSP).
// d in four 64-chunks; accumulators persist in registers so each packed lane
// remains ONE sequential FFMA chain over d=0..255 (bit-identical to ref).
// Per thread 8x8 micro-tile: 32 FFMA2 from 4 LDS.128 per d = crossbar/fma
// balance point; 2 resident CTAs cover staging latency.
// ---------------------------------------------------------------------------
// smem floats: Xs(DCH*XS_STR) Ds(DCH*DS_STR) se(BK) bestsh(BM ull)
#define SMEM_FLOATS (DCH * XS_STR + DCH * DS_STR + BK + 2 * BM)
#define SMEM_BYTES  (SMEM_FLOATS * 4)

extern __shared__ float smem_f[];

__global__ void __launch_bounds__(TPB, 2) vq_main(const float* __restrict__ dict) {
    float* Xs = smem_f;
    float* Ds = Xs + DCH * XS_STR;
    float* se = Ds + DCH * DS_STR;
    unsigned long long* bestsh = (unsigned long long*)(se + BK);

    const int tid = threadIdx.x;
    const int rt  = blockIdx.x >> 3;         // row tile (adjacent bids share rt -> L2 reuse)
    const int cc  = blockIdx.x & 7;          // code chunk
    const int m0  = rt * BM;
    const int k0  = cc * BK;

    if (tid < BK) se[tid] = g_sume2[k0 + tid];
    if (tid < BM) bestsh[tid] = 0xFFFFFFFFFFFFFFFFull;

    const int tx = tid & 15;    // 16 code groups x 8 codes = 128 (BK)
    const int ty = tid >> 4;    // 16 row groups  x 8 rows  = 128 (BM)

    // acc2[rowpair][code]: packed lanes = (row ty*8+2rp, +2rp+1)
    unsigned long long acc2[4][8];
    #pragma unroll
    for (int i = 0; i < 4; i++)
        #pragma unroll
        for (int j = 0; j < 8; j++) acc2[i][j] = 0ULL;

    for (int ch = 0; ch < DIM / DCH; ch++) {
        __syncthreads();    // protect smem reuse from previous chunk

        // Xs chunk: straight copy from g_xT (conflict-free both sides)
        #pragma unroll 2
        for (int t = tid; t < DCH * (BM / 4); t += TPB) {
            int d  = t >> 5;            // 32 float4 per d-row
            int m4 = t & 31;
            *(float4*)&Xs[d * XS_STR + m4 * 4] =
                *(const float4*)&g_xT[(size_t)(ch * DCH + d) * N_ROWS + m0 + m4 * 4];
        }
        // Ds chunk, split-half layout: codes j<4 of group g at col g*4,
        // j>=4 at 64 + g*4  -> both b-loads are 16B-stride, conflict-free
        #pragma unroll 2
        for (int t = tid; t < DCH * (BK / 4); t += TPB) {
            int d  = t >> 5;
            int k4 = t & 31;
            int col = ((k4 & 1) << 6) + ((k4 >> 1) << 2);
            *(float4*)&Ds[d * DS_STR + col] =
                *(const float4*)&dict[(size_t)(ch * DCH + d) * NCODES + k0 + k4 * 4];
        }
        __syncthreads();

        #pragma unroll 1
        for (int d = 0; d < DCH; d++) {
            ulonglong2 a01 = *(const ulonglong2*)&Xs[d * XS_STR + ty * 8];
            ulonglong2 a23 = *(const ulonglong2*)&Xs[d * XS_STR + ty * 8 + 4];
            float4 bA = *(const float4*)&Ds[d * DS_STR + tx * 4];
            float4 bB = *(const float4*)&Ds[d * DS_STR + 64 + tx * 4];
            unsigned long long b0 = bcast2(bA.x);
            unsigned long long b1 = bcast2(bA.y);
            unsigned long long b2 = bcast2(bA.z);
            unsigned long long b3 = bcast2(bA.w);
            unsigned long long b4 = bcast2(bB.x);
            unsigned long long b5 = bcast2(bB.y);
            unsigned long long b6 = bcast2(bB.z);
            unsigned long long b7 = bcast2(bB.w);
            ffma2(acc2[0][0], a01.x, b0); ffma2(acc2[0][1], a01.x, b1);
            ffma2(acc2[0][2], a01.x, b2); ffma2(acc2[0][3], a01.x, b3);
            ffma2(acc2[0][4], a01.x, b4); ffma2(acc2[0][5], a01.x, b5);
            ffma2(acc2[0][6], a01.x, b6); ffma2(acc2[0][7], a01.x, b7);
            ffma2(acc2[1][0], a01.y, b0); ffma2(acc2[1][1], a01.y, b1);
            ffma2(acc2[1][2], a01.y, b2); ffma2(acc2[1][3], a01.y, b3);
            ffma2(acc2[1][4], a01.y, b4); ffma2(acc2[1][5], a01.y, b5);
            ffma2(acc2[1][6], a01.y, b6); ffma2(acc2[1][7], a01.y, b7);
            ffma2(acc2[2][0], a23.x, b0); ffma2(acc2[2][1], a23.x, b1);
            ffma2(acc2[2][2], a23.x, b2); ffma2(acc2[2][3], a23.x, b3);
            ffma2(acc2[2][4], a23.x, b4); ffma2(acc2[2][5], a23.x, b5);
            ffma2(acc2[2][6], a23.x, b6); ffma2(acc2[2][7], a23.x, b7);
            ffma2(acc2[3][0], a23.y, b0); ffma2(acc2[3][1], a23.y, b1);
            ffma2(acc2[3][2], a23.y, b2); ffma2(acc2[3][3], a23.y, b3);
            ffma2(acc2[3][4], a23.y, b4); ffma2(acc2[3][5], a23.y, b5);
            ffma2(acc2[3][6], a23.y, b6); ffma2(acc2[3][7], a23.y, b7);
        }
    }

    // reference-exact distance: D = fl( fl(S + se_k) - 2*sim ), argmin w/ index
    float Srow[8];
    #pragma unroll
    for (int i = 0; i < 8; i++) Srow[i] = g_S[m0 + ty * 8 + i];

    unsigned long long kmin[8];
    #pragma unroll
    for (int i = 0; i < 8; i++) kmin[i] = 0xFFFFFFFFFFFFFFFFull;

    #pragma unroll
    for (int rp = 0; rp < 4; rp++) {
        #pragma unroll
        for (int j = 0; j < 8; j++) {
            int k = k0 + tx * 8 + j;
            float slo, shi;
            unpack2(acc2[rp][j], slo, shi);
            float T0 = __fadd_rn(Srow[rp * 2 + 0], se[tx * 8 + j]);
            float D0 = __fadd_rn(T0, -2.0f * slo);
            unsigned long long key0 =
                ((unsigned long long)enc_f(D0) << 32) | (unsigned long long)(unsigned)k;
            if (key0 < kmin[rp * 2 + 0]) kmin[rp * 2 + 0] = key0;
            float T1 = __fadd_rn(Srow[rp * 2 + 1], se[tx * 8 + j]);
            float D1 = __fadd_rn(T1, -2.0f * shi);
            unsigned long long key1 =
                ((unsigned long long)enc_f(D1) << 32) | (unsigned long long)(unsigned)k;
            if (key1 < kmin[rp * 2 + 1]) kmin[rp * 2 + 1] = key1;
        }
    }

    // block-local merge (order-independent min), then one global atomic per row
    #pragma unroll
    for (int i = 0; i < 8; i++) atomicMin(&bestsh[ty * 8 + i], kmin[i]);
    __syncthreads();
    if (tid < BM) atomicMin(&g_best[m0 + tid], bestsh[tid]);
}

// ---------------------------------------------------------------------------
// Gather: codes -> quantized output + per-tile loss partial (deterministic)
// ---------------------------------------------------------------------------
__global__ void __launch_bounds__(GTPB) vq_gather(const float* __restrict__ x,
                                                  float* __restrict__ out) {
    __shared__ int codes[BM];
    __shared__ float redf[GTPB];
    const int tid = threadIdx.x;
    const int m0  = blockIdx.x * BM;

    if (tid < BM)
        codes[tid] = (int)(unsigned)(g_best[m0 + tid] & 0xFFFFFFFFull);
    __syncthreads();

    const float4* x4 = (const float4*)x;
    float4* out4 = (float4*)out;
    float lsum = 0.0f;
    #pragma unroll 4
    for (int t = tid; t < BM * DIM / 4; t += GTPB) {
        int m  = t >> 6;
        int d4 = t & 63;
        float4 v  = *(const float4*)&g_dictT[codes[m] * DIM + d4 * 4];
        size_t gi = (size_t)(m0 + m) * (DIM / 4) + d4;
        float4 xv = x4[gi];
        float dx = xv.x - v.x, dy = xv.y - v.y, dz = xv.z - v.z, dw = xv.w - v.w;
        lsum += dx * dx + dy * dy + dz * dz + dw * dw;
        out4[gi] = v;
    }
    redf[tid] = lsum;
    __syncthreads();
    #pragma unroll
    for (int s = GTPB / 2; s > 0; s >>= 1) {
        if (tid < s) redf[tid] += redf[tid + s];
        __syncthreads();
    }
    if (tid == 0) g_partial[blockIdx.x] = redf[0];
}

// ---------------------------------------------------------------------------
// Final loss: loss = fl( m + fl(0.25*m) ), m = mean((x-q)^2) (f64 reduce)
// ---------------------------------------------------------------------------
__global__ void vq_finish(float* __restrict__ out, int out_size) {
    __shared__ double rd[GTPB];
    int tid = threadIdx.x;
    double s = 0.0;
    for (int i = tid; i < NTILES; i += GTPB) s += (double)g_partial[i];
    rd[tid] = s;
    __syncthreads();
    #pragma unroll
    for (int st = GTPB / 2; st > 0; st >>= 1) {
        if (tid < st) rd[tid] += rd[tid + st];
        __syncthreads();
    }
    if (tid == 0 && out_size > N_ROWS * DIM) {
        double mse = rd[0] / (double)((size_t)N_ROWS * DIM);
        float m = (float)mse;
        out[N_ROWS * DIM] = __fadd_rn(m, __fmul_rn(0.25f, m));
    }
}

// ---------------------------------------------------------------------------
extern "C" void kernel_launch(void* const* d_in, const int* in_sizes, int n_in,
                              void* d_out, int out_size) {
    const float* x    = (const float*)d_in[0];   // [16,64,64,256] f32
    const float* dict = (const float*)d_in[1];   // [256,1024]     f32
    float* out = (float*)d_out;

    cudaFuncSetAttribute(vq_main, cudaFuncAttributeMaxDynamicSharedMemorySize, SMEM_BYTES);

    vq_transpose<<<NCODES, DIM>>>(dict);
    vq_sume2<<<NCODES / GTPB, GTPB>>>(dict);
    {
        dim3 tb(32, 8);
        dim3 tg(N_ROWS / 32, DIM / 32);
        vq_xT<<<tg, tb>>>(x);
    }
    vq_rownorm<<<N_ROWS / 32, 256>>>(x);
    vq_reset<<<N_ROWS / GTPB, GTPB>>>();
    vq_main<<<NBLOCKS_MAIN, TPB, SMEM_BYTES>>>(dict);
    vq_gather<<<NTILES, GTPB>>>(x, out);
    vq_finish<<<1, GTPB>>>(out, out_size);
}

// round 16
// speedup vs baseline: 1.2040x; 1.1106x over previous
#include <cuda_runtime.h>
#include <cuda_bf16.h>
#include <cstdint>

#define N_ROWS   65536
#define DIM      256
#define NCODES   1024
#define BM       128
#define TPB      256
#define GTPB     256
#define NTILES   (N_ROWS / BM)   // 512
#define MARGIN_F 0.01f

// ---- device scratch (no allocation anywhere) ----
// A fragments: [tile][kstep 16][mfrag 8][lane 32] uint4 = {a0,a1,a2,a3}
__device__ uint4 g_Ah[(size_t)NTILES * 4096];
__device__ uint4 g_Al[(size_t)NTILES * 4096];
// B fragments: [nfrag 128][kstep 16][lane 32] uint2 = {b0,b1}
__device__ uint2 g_Bh[128 * 16 * 32];
__device__ uint2 g_Bl[128 * 16 * 32];
__device__ float g_dictT[NCODES * DIM];     // [k][d] for gather
__device__ float g_sume2[NCODES];           // fl32 sequential sum e^2 (ref-exact)
__device__ float g_S[N_ROWS];               // ref-emulated row norms
__device__ int   g_code[N_ROWS];
__device__ int   g_flagrows[N_ROWS];
__device__ int   g_nflag;
__device__ float g_partial[NTILES];

// =========================== init kernels ==================================
__global__ void vq_transpose(const float* __restrict__ dict) {
    int k = blockIdx.x, d = threadIdx.x;
    g_dictT[k * DIM + d] = dict[d * NCODES + k];
}
__global__ void vq_sume2(const float* __restrict__ dict) {
    int k = blockIdx.x * blockDim.x + threadIdx.x;
    if (k >= NCODES) return;
    float s = 0.0f;
    for (int d = 0; d < DIM; d++) {
        float e = dict[d * NCODES + k];
        s = __fadd_rn(s, __fmul_rn(e, e));
    }
    g_sume2[k] = s;
}
// S = sum(x_row^2): bit-exact XLA warp row-reduce (validated R7)
__global__ void vq_rownorm(const float* __restrict__ x) {
    int warp = threadIdx.x >> 5, lane = threadIdx.x & 31;
    int row0 = blockIdx.x * 32 + warp * 4;
    #pragma unroll
    for (int r = 0; r < 4; r++) {
        int row = row0 + r;
        float p = 0.0f;
        #pragma unroll
        for (int i = 0; i < 8; i++) {
            float v = x[(size_t)row * DIM + lane + 32 * i];
            p = __fadd_rn(p, __fmul_rn(v, v));
        }
        #pragma unroll
        for (int o = 16; o > 0; o >>= 1)
            p = __fadd_rn(p, __shfl_xor_sync(0xFFFFFFFFu, p, o));
        if (lane == 0) g_S[row] = p;
    }
}
__global__ void vq_reset0() { if (threadIdx.x == 0) g_nflag = 0; }

// bf16 hi/lo split of a float pair -> packed bf16x2 words
__device__ __forceinline__ void split2(float v0, float v1, unsigned& hi, unsigned& lo) {
    __nv_bfloat16 h0 = __float2bfloat16(v0), h1 = __float2bfloat16(v1);
    __nv_bfloat16 l0 = __float2bfloat16(v0 - __bfloat162float(h0));
    __nv_bfloat16 l1 = __float2bfloat16(v1 - __bfloat162float(h1));
    hi = (unsigned)__bfloat16_as_ushort(h0) | ((unsigned)__bfloat16_as_ushort(h1) << 16);
    lo = (unsigned)__bfloat16_as_ushort(l0) | ((unsigned)__bfloat16_as_ushort(l1) << 16);
}

// A pack: mma m16n8k16 A frag (row-major): lane(g=l>>2,t=l&3):
//   a0={A[g][t2],A[g][t2+1]} a1={A[g+8][t2],..} a2={A[g][t2+8],..} a3={A[g+8][t2+8],..}
__global__ void vq_packA(const float* __restrict__ x) {
    int idx  = blockIdx.x * 256 + threadIdx.x;      // 512*4096
    int lane = idx & 31;
    int mf   = (idx >> 5) & 7;
    int ks   = (idx >> 8) & 15;
    int tile = idx >> 12;
    int g = lane >> 2, t = lane & 3;
    const float* r0 = x + (size_t)(tile * 128 + mf * 16 + g) * DIM;
    const float* r1 = r0 + 8 * DIM;
    int kb = ks * 16 + t * 2;
    uint4 H, L;
    split2(r0[kb],     r0[kb + 1], H.x, L.x);
    split2(r1[kb],     r1[kb + 1], H.y, L.y);
    split2(r0[kb + 8], r0[kb + 9], H.z, L.z);
    split2(r1[kb + 8], r1[kb + 9], H.w, L.w);
    g_Ah[idx] = H;
    g_Al[idx] = L;
}
// B pack: mma B frag (col-major k16n8): b0={B[t2][g],B[t2+1][g]} b1={B[t2+8][g],..}
// B[k][n] = dict[k][code], code = nf*8+g
__global__ void vq_packB(const float* __restrict__ dict) {
    int idx  = blockIdx.x * 256 + threadIdx.x;      // 128*16*32 = 65536
    int lane = idx & 31;
    int ks   = (idx >> 5) & 15;
    int nf   = idx >> 9;
    int g = lane >> 2, t = lane & 3;
    int code = nf * 8 + g;
    int k0 = ks * 16 + t * 2;
    unsigned h0, l0, h1, l1;
    split2(dict[(size_t)k0 * NCODES + code],       dict[(size_t)(k0 + 1) * NCODES + code], h0, l0);
    split2(dict[(size_t)(k0 + 8) * NCODES + code], dict[(size_t)(k0 + 9) * NCODES + code], h1, l1);
    g_Bh[idx] = make_uint2(h0, h1);
    g_Bl[idx] = make_uint2(l0, l1);
}

// =========================== main: HMMA filter =============================
__device__ __forceinline__ void mma16816(float* c, const unsigned* a, const unsigned* b) {
    asm volatile(
        "mma.sync.aligned.m16n8k16.row.col.f32.bf16.bf16.f32 "
        "{%0,%1,%2,%3}, {%4,%5,%6,%7}, {%8,%9}, {%0,%1,%2,%3};"
        : "+f"(c[0]), "+f"(c[1]), "+f"(c[2]), "+f"(c[3])
        : "r"(a[0]), "r"(a[1]), "r"(a[2]), "r"(a[3]), "r"(b[0]), "r"(b[1]));
}

// smem: Ah 64K | Al 64K | se 4K | merge m1 2K | m2 2K | mk 2K
#define SM_AH   0
#define SM_AL   65536
#define SM_SE   131072
#define SM_M1   135168
#define SM_M2   137216
#define SM_MK   139264
#define SMEM_MAIN 141312

extern __shared__ char smc[];

__global__ void __launch_bounds__(TPB, 1) vq_main() {
    uint4* Ah_s = (uint4*)(smc + SM_AH);
    uint4* Al_s = (uint4*)(smc + SM_AL);
    float* se   = (float*)(smc + SM_SE);
    float* sm1  = (float*)(smc + SM_M1);
    float* sm2  = (float*)(smc + SM_M2);
    int*   smk  = (int*)(smc + SM_MK);

    const int tid = threadIdx.x, lane = tid & 31, wid = tid >> 5;
    const int g = lane >> 2, t = lane & 3;
    const int wm = wid & 1;        // m half (m64)
    const int wn = wid >> 1;       // n quarter (n32 per n-block)
    const int tile = blockIdx.x;

    // stage A frags + se
    {
        const uint4* sH = g_Ah + (size_t)tile * 4096;
        const uint4* sL = g_Al + (size_t)tile * 4096;
        #pragma unroll 4
        for (int i = tid; i < 4096; i += TPB) { Ah_s[i] = sH[i]; Al_s[i] = sL[i]; }
        for (int i = tid; i < NCODES; i += TPB) se[i] = g_sume2[i];
    }
    __syncthreads();

    // per-thread rows: slot s = mf*2+half -> row = wm*64+mf*16+half*8+g
    float Sv[8];
    #pragma unroll
    for (int mf = 0; mf < 4; mf++) {
        Sv[mf * 2 + 0] = g_S[tile * 128 + wm * 64 + mf * 16 + g];
        Sv[mf * 2 + 1] = g_S[tile * 128 + wm * 64 + mf * 16 + 8 + g];
    }
    float mn1[8], mn2[8];
    int   bk[8];
    #pragma unroll
    for (int i = 0; i < 8; i++) { mn1[i] = 3.4e38f; mn2[i] = 3.4e38f; bk[i] = 0; }

    for (int nb = 0; nb < 8; nb++) {               // 8 n-blocks of 128 codes
        const int nfbase = nb * 16 + wn * 4;       // this warp's 4 n-frags
        float acc[4][4][4];
        #pragma unroll
        for (int i = 0; i < 4; i++)
            #pragma unroll
            for (int j = 0; j < 4; j++)
                #pragma unroll
                for (int q = 0; q < 4; q++) acc[i][j][q] = 0.0f;

        #pragma unroll 2
        for (int ks = 0; ks < 16; ks++) {
            unsigned ah[4][4], al[4][4], bh[4][2], bl[4][2];
            #pragma unroll
            for (int mf = 0; mf < 4; mf++) {
                uint4 vh = Ah_s[(ks * 8 + wm * 4 + mf) * 32 + lane];
                ah[mf][0] = vh.x; ah[mf][1] = vh.y; ah[mf][2] = vh.z; ah[mf][3] = vh.w;
                uint4 vl = Al_s[(ks * 8 + wm * 4 + mf) * 32 + lane];
                al[mf][0] = vl.x; al[mf][1] = vl.y; al[mf][2] = vl.z; al[mf][3] = vl.w;
            }
            #pragma unroll
            for (int nf = 0; nf < 4; nf++) {
                uint2 vb = g_Bh[((nfbase + nf) * 16 + ks) * 32 + lane];
                bh[nf][0] = vb.x; bh[nf][1] = vb.y;
                uint2 vc = g_Bl[((nfbase + nf) * 16 + ks) * 32 + lane];
                bl[nf][0] = vc.x; bl[nf][1] = vc.y;
            }
            #pragma unroll
            for (int mf = 0; mf < 4; mf++)
                #pragma unroll
                for (int nf = 0; nf < 4; nf++) {
                    mma16816(acc[mf][nf], ah[mf], bh[nf]);   // hi*hi
                    mma16816(acc[mf][nf], al[mf], bh[nf]);   // lo*hi
                    mma16816(acc[mf][nf], ah[mf], bl[nf]);   // hi*lo
                }
        }

        // epilogue: D = S + se - 2*sim ; top-2 per row
        #pragma unroll
        for (int mf = 0; mf < 4; mf++)
            #pragma unroll
            for (int nf = 0; nf < 4; nf++) {
                int c0 = nb * 128 + wn * 32 + nf * 8 + t * 2;
                float se0 = se[c0], se1 = se[c0 + 1];
                float D00 = fmaf(-2.0f, acc[mf][nf][0], Sv[mf * 2] + se0);
                float D01 = fmaf(-2.0f, acc[mf][nf][1], Sv[mf * 2] + se1);
                float D10 = fmaf(-2.0f, acc[mf][nf][2], Sv[mf * 2 + 1] + se0);
                float D11 = fmaf(-2.0f, acc[mf][nf][3], Sv[mf * 2 + 1] + se1);
                int s0 = mf * 2, s1 = mf * 2 + 1;
                if (D00 < mn1[s0]) { mn2[s0] = mn1[s0]; mn1[s0] = D00; bk[s0] = c0; }
                else if (D00 < mn2[s0]) mn2[s0] = D00;
                if (D01 < mn1[s0]) { mn2[s0] = mn1[s0]; mn1[s0] = D01; bk[s0] = c0 + 1; }
                else if (D01 < mn2[s0]) mn2[s0] = D01;
                if (D10 < mn1[s1]) { mn2[s1] = mn1[s1]; mn1[s1] = D10; bk[s1] = c0; }
                else if (D10 < mn2[s1]) mn2[s1] = D10;
                if (D11 < mn1[s1]) { mn2[s1] = mn1[s1]; mn1[s1] = D11; bk[s1] = c0 + 1; }
                else if (D11 < mn2[s1]) mn2[s1] = D11;
            }
    }

    // merge top-2 across the 4 lanes (t) sharing each row
    #pragma unroll
    for (int s = 0; s < 8; s++) {
        #pragma unroll
        for (int off = 1; off < 4; off <<= 1) {
            float o1 = __shfl_xor_sync(0xFFFFFFFFu, mn1[s], off);
            float o2 = __shfl_xor_sync(0xFFFFFFFFu, mn2[s], off);
            int   ok = __shfl_xor_sync(0xFFFFFFFFu, bk[s], off);
            if (o1 < mn1[s]) { mn2[s] = fminf(mn1[s], o2); mn1[s] = o1; bk[s] = ok; }
            else             { mn2[s] = fminf(mn2[s], o1); }
        }
    }
    if (t == 0) {
        #pragma unroll
        for (int s = 0; s < 8; s++) {
            int row = wm * 64 + (s >> 1) * 16 + (s & 1) * 8 + g;
            sm1[row * 4 + wn] = mn1[s];
            sm2[row * 4 + wn] = mn2[s];
            smk[row * 4 + wn] = bk[s];
        }
    }
    __syncthreads();

    // final per-row merge across the 4 n-warps; flag or commit
    if (tid < 128) {
        float m1 = sm1[tid * 4], m2 = sm2[tid * 4];
        int   kk = smk[tid * 4];
        #pragma unroll
        for (int w = 1; w < 4; w++) {
            float o1 = sm1[tid * 4 + w], o2 = sm2[tid * 4 + w];
            int   ok = smk[tid * 4 + w];
            if (o1 < m1) { m2 = fminf(m1, o2); m1 = o1; kk = ok; }
            else         { m2 = fminf(m2, o1); }
        }
        int row_g = tile * 128 + tid;
        if (m2 - m1 < MARGIN_F) {
            int ix = atomicAdd(&g_nflag, 1);
            g_flagrows[ix] = row_g;
        } else {
            g_code[row_g] = kk;   // provably the unique reference argmin
        }
    }
}

// ============== exact rescore for ambiguous rows (R7-validated recipe) =====
__global__ void __launch_bounds__(TPB) vq_exact(const float* __restrict__ x,
                                                const float* __restrict__ dict) {
    __shared__ float xs[DIM];
    __shared__ unsigned long long sbest;
    const int tid = threadIdx.x;

    for (int i = blockIdx.x; i < g_nflag; i += gridDim.x) {
        int row = g_flagrows[i];
        __syncthreads();
        if (tid < DIM) xs[tid] = x[(size_t)row * DIM + tid];
        if (tid == 0) sbest = 0xFFFFFFFFFFFFFFFFull;
        __syncthreads();

        float S = g_S[row];
        #pragma unroll
        for (int j = 0; j < NCODES / TPB; j++) {
            int k = j * TPB + tid;
            float s = 0.0f;
            #pragma unroll 4
            for (int d = 0; d < DIM; d++)
                s = __fmaf_rn(xs[d], dict[d * NCODES + k], s);   // sequential FFMA chain
            float T = __fadd_rn(S, g_sume2[k]);
            float D = __fadd_rn(T, -2.0f * s);                   // reference-exact rounding
            unsigned u = __float_as_uint(D);
            u = (u & 0x80000000u) ? ~u : (u | 0x80000000u);
            unsigned long long key = ((unsigned long long)u << 32) | (unsigned)k;
            atomicMin(&sbest, key);
        }
        __syncthreads();
        if (tid == 0) g_code[row] = (int)(unsigned)(sbest & 0xFFFFFFFFull);
    }
}

// ====================== gather + loss ======================================
__global__ void __launch_bounds__(GTPB) vq_gather(const float* __restrict__ x,
                                                  float* __restrict__ out) {
    __shared__ int codes[BM];
    __shared__ float redf[GTPB];
    const int tid = threadIdx.x;
    const int m0  = blockIdx.x * BM;
    if (tid < BM) codes[tid] = g_code[m0 + tid];
    __syncthreads();

    const float4* x4 = (const float4*)x;
    float4* out4 = (float4*)out;
    float lsum = 0.0f;
    #pragma unroll 4
    for (int t = tid; t < BM * DIM / 4; t += GTPB) {
        int m  = t >> 6;
        int d4 = t & 63;
        float4 v  = *(const float4*)&g_dictT[codes[m] * DIM + d4 * 4];
        size_t gi = (size_t)(m0 + m) * (DIM / 4) + d4;
        float4 xv = x4[gi];
        float dx = xv.x - v.x, dy = xv.y - v.y, dz = xv.z - v.z, dw = xv.w - v.w;
        lsum += dx * dx + dy * dy + dz * dz + dw * dw;
        out4[gi] = v;
    }
    redf[tid] = lsum;
    __syncthreads();
    #pragma unroll
    for (int s = GTPB / 2; s > 0; s >>= 1) {
        if (tid < s) redf[tid] += redf[tid + s];
        __syncthreads();
    }
    if (tid == 0) g_partial[blockIdx.x] = redf[0];
}

__global__ void vq_finish(float* __restrict__ out, int out_size) {
    __shared__ double rd[GTPB];
    int tid = threadIdx.x;
    double s = 0.0;
    for (int i = tid; i < NTILES; i += GTPB) s += (double)g_partial[i];
    rd[tid] = s;
    __syncthreads();
    #pragma unroll
    for (int st = GTPB / 2; st > 0; st >>= 1) {
        if (tid < st) rd[tid] += rd[tid + st];
        __syncthreads();
    }
    if (tid == 0 && out_size > N_ROWS * DIM) {
        double mse = rd[0] / (double)((size_t)N_ROWS * DIM);
        float m = (float)mse;
        out[N_ROWS * DIM] = __fadd_rn(m, __fmul_rn(0.25f, m));
    }
}

// ---------------------------------------------------------------------------
extern "C" void kernel_launch(void* const* d_in, const int* in_sizes, int n_in,
                              void* d_out, int out_size) {
    const float* x    = (const float*)d_in[0];   // [16,64,64,256] f32
    const float* dict = (const float*)d_in[1];   // [256,1024]     f32
    float* out = (float*)d_out;

    cudaFuncSetAttribute(vq_main, cudaFuncAttributeMaxDynamicSharedMemorySize, SMEM_MAIN);

    vq_transpose<<<NCODES, DIM>>>(dict);
    vq_sume2<<<NCODES / GTPB, GTPB>>>(dict);
    vq_rownorm<<<N_ROWS / 32, 256>>>(x);
    vq_reset0<<<1, 32>>>();
    vq_packA<<<NTILES * 16, 256>>>(x);
    vq_packB<<<256, 256>>>(dict);
    vq_main<<<NTILES, TPB, SMEM_MAIN>>>();
    vq_exact<<<256, TPB>>>(x, dict);
    vq_gather<<<NTILES, GTPB>>>(x, out);
    vq_finish<<<1, GTPB>>>(out, out_size);
}